// round 7
// baseline (speedup 1.0000x reference)
#include <cuda_runtime.h>

#define DM    64
#define NPTS  1323
#define NTHR  256

// exact p/1323 for p < ~2^31 (magic: ceil(2^40/1323) = 831074549)
__device__ __forceinline__ unsigned rowof(unsigned p) {
    return (unsigned)(((unsigned long long)p * 831074549ull) >> 40);
}

// one point through the inverse-Cholesky transform + gaussian
__device__ __forceinline__ float mvn_pt(float d0, float d1, float d2,
                                        float4 qa, float4 qb, float2 qc)
{
    d0 -= qa.x;
    d1 -= qa.y;
    d2 -= qa.z;
    float z0 = d0 * qa.w;
    float z1 = (d1 - qb.x * z0) * qb.y;
    float z2 = fmaf(-qb.w, z1, fmaf(-qb.z, z0, d2)) * qc.x;
    float maha = fmaf(z0, z0, fmaf(z1, z1, z2 * z2));
    return qc.y * __expf(-0.5f * maha);
}

// one slot (4 points in 3 float4), params selected from the warp's two row-sets
__device__ __forceinline__ float4 mvn_slot(
    unsigned s, float4 a, float4 b, float4 c, unsigned r_lo,
    float4 q0a, float4 q0b, float2 q0c,
    float4 q1a, float4 q1b, float2 q1c)
{
    const unsigned p0 = 4u * s;
    const unsigned r0 = rowof(p0);
    const unsigned r3 = rowof(p0 + 3u);

    const bool lo0 = (r0 == r_lo);
    const float4 qa = lo0 ? q0a : q1a;
    const float4 qb = lo0 ? q0b : q1b;
    const float2 qc = lo0 ? q0c : q1c;

    float4 res;
    if (r0 == r3) {
        // fast path (99.7%)
        res.x = mvn_pt(a.x, a.y, a.z, qa, qb, qc);
        res.y = mvn_pt(a.w, b.x, b.y, qa, qb, qc);
        res.z = mvn_pt(b.z, b.w, c.x, qa, qb, qc);
        res.w = mvn_pt(c.y, c.z, c.w, qa, qb, qc);
    } else {
        // slot crosses a row boundary: points >= E use row r3's params
        const unsigned E = (r0 + 1u) * (unsigned)NPTS;
        const bool lo3 = (r3 == r_lo);
        const float4 qa2 = lo3 ? q0a : q1a;
        const float4 qb2 = lo3 ? q0b : q1b;
        const float2 qc2 = lo3 ? q0c : q1c;
        res.x = (p0 + 0 < E) ? mvn_pt(a.x, a.y, a.z, qa, qb, qc)
                             : mvn_pt(a.x, a.y, a.z, qa2, qb2, qc2);
        res.y = (p0 + 1 < E) ? mvn_pt(a.w, b.x, b.y, qa, qb, qc)
                             : mvn_pt(a.w, b.x, b.y, qa2, qb2, qc2);
        res.z = (p0 + 2 < E) ? mvn_pt(b.z, b.w, c.x, qa, qb, qc)
                             : mvn_pt(b.z, b.w, c.x, qa2, qb2, qc2);
        res.w = (p0 + 3 < E) ? mvn_pt(c.y, c.z, c.w, qa, qb, qc)
                             : mvn_pt(c.y, c.z, c.w, qa2, qb2, qc2);
    }
    return res;
}

__global__ __launch_bounds__(NTHR) void mvn_fused_kernel(
    const float* __restrict__ rep,
    const float* __restrict__ dxyz,
    const float* __restrict__ Wm,
    const float* __restrict__ bm,
    const float* __restrict__ Ws,
    const float* __restrict__ bs,
    float* __restrict__ out)
{
    const int t = threadIdx.x;
    const int lane = t & 31;

    const unsigned s0 = blockIdx.x * (2u * NTHR) + (unsigned)t;   // slot 0
    const unsigned s1 = s0 + NTHR;                                // slot 1 (coalesced)

    // ---- issue the 6 streaming loads FIRST; params compute under their latency ----
    const float4* __restrict__ dp0 = (const float4*)dxyz + 3u * (size_t)s0;
    const float4* __restrict__ dp1 = (const float4*)dxyz + 3u * (size_t)s1;
    const float4 a0 = __ldcs(dp0 + 0);
    const float4 b0 = __ldcs(dp0 + 1);
    const float4 c0 = __ldcs(dp0 + 2);
    const float4 a1 = __ldcs(dp1 + 0);
    const float4 b1 = __ldcs(dp1 + 1);
    const float4 c1 = __ldcs(dp1 + 2);

    // ---- warp's two rows: slots [sw, sw+31] and [sw+256, sw+287] -> <=2 rows ----
    const unsigned sw   = blockIdx.x * (2u * NTHR) + (unsigned)(t & ~31);
    const unsigned r_lo = rowof(4u * sw);
    const unsigned r_hi = rowof(4u * (sw + NTHR + 31u) + 3u);

    // 9 dot products for each of the two rows, butterfly-reduced (no barriers)
    const float2 rv0 = ((const float2*)(rep + (size_t)r_lo * DM))[lane];
    const float2 rv1 = ((const float2*)(rep + (size_t)r_hi * DM))[lane];

    float m00, m01, m02, m10, m11, m12;          // mean dots (all lanes)
    float my0 = 0.0f, my1 = 0.0f;                // lane ℓ<6 holds scale-dot ℓ
    #pragma unroll
    for (int c = 0; c < 9; c++) {
        const float* w = (c < 3) ? (Wm + c * DM) : (Ws + (c - 3) * DM);
        const float2 wv = ((const float2*)w)[lane];
        float p0v = fmaf(rv0.x, wv.x, rv0.y * wv.y);
        float p1v = fmaf(rv1.x, wv.x, rv1.y * wv.y);
        #pragma unroll
        for (int off = 16; off > 0; off >>= 1) {
            p0v += __shfl_xor_sync(0xFFFFFFFFu, p0v, off);
            p1v += __shfl_xor_sync(0xFFFFFFFFu, p1v, off);
        }
        if      (c == 0) { m00 = p0v; m10 = p1v; }
        else if (c == 1) { m01 = p0v; m11 = p1v; }
        else if (c == 2) { m02 = p0v; m12 = p1v; }
        else {
            my0 = (lane == c - 3) ? p0v : my0;
            my1 = (lane == c - 3) ? p1v : my1;
        }
    }

    // lanes 0..5: sigmoid + softplus + reciprocal for both rows (fast-math)
    const int ci = (lane < 6) ? lane : 0;
    const float bsv = __ldg(bs + ci);
    const float sig0 = __fdividef(1.0f, 1.0f + __expf(-(my0 + bsv)));
    const float sig1 = __fdividef(1.0f, 1.0f + __expf(-(my1 + bsv)));
    const float sp0  = __logf(1.0f + __expf(sig0));   // sig in (0,1): safe
    const float sp1  = __logf(1.0f + __expf(sig1));
    const float iv0  = __fdividef(1.0f, sp0);
    const float iv1  = __fdividef(1.0f, sp1);

    // broadcast the 6 scale params per row
    const float i00 = __shfl_sync(0xFFFFFFFFu, iv0, 0);
    const float s10 = __shfl_sync(0xFFFFFFFFu, sig0, 1);
    const float i11 = __shfl_sync(0xFFFFFFFFu, iv0, 2);
    const float s20 = __shfl_sync(0xFFFFFFFFu, sig0, 3);
    const float s21 = __shfl_sync(0xFFFFFFFFu, sig0, 4);
    const float i22 = __shfl_sync(0xFFFFFFFFu, iv0, 5);
    const float j00 = __shfl_sync(0xFFFFFFFFu, iv1, 0);
    const float t10 = __shfl_sync(0xFFFFFFFFu, sig1, 1);
    const float j11 = __shfl_sync(0xFFFFFFFFu, iv1, 2);
    const float t20 = __shfl_sync(0xFFFFFFFFu, sig1, 3);
    const float t21 = __shfl_sync(0xFFFFFFFFu, sig1, 4);
    const float j22 = __shfl_sync(0xFFFFFFFFu, iv1, 5);

    const float INVK = 0.06349363593424098f;          // 1/(2*pi)^1.5
    const float bm0 = __ldg(bm + 0), bm1 = __ldg(bm + 1), bm2 = __ldg(bm + 2);

    const float4 q0a = make_float4(m00 + bm0, m01 + bm1, m02 + bm2, i00);
    const float4 q0b = make_float4(s10, i11, s20, s21);
    const float2 q0c = make_float2(i22, i00 * i11 * i22 * INVK);
    const float4 q1a = make_float4(m10 + bm0, m11 + bm1, m12 + bm2, j00);
    const float4 q1b = make_float4(t10, j11, t20, t21);
    const float2 q1c = make_float2(j22, j00 * j11 * j22 * INVK);

    // ---- compute + store ----
    const float4 r0 = mvn_slot(s0, a0, b0, c0, r_lo, q0a, q0b, q0c, q1a, q1b, q1c);
    const float4 r1 = mvn_slot(s1, a1, b1, c1, r_lo, q0a, q0b, q0c, q1a, q1b, q1c);

    __stcs((float4*)out + s0, r0);
    __stcs((float4*)out + s1, r1);
}

extern "C" void kernel_launch(void* const* d_in, const int* in_sizes, int n_in,
                              void* d_out, int out_size)
{
    const float* rep  = (const float*)d_in[0];
    const float* dxyz = (const float*)d_in[1];
    const float* Wm   = (const float*)d_in[2];
    const float* bm   = (const float*)d_in[3];
    const float* Ws   = (const float*)d_in[4];
    const float* bs   = (const float*)d_in[5];
    // d_in[6] = num_planes (fixed 3) — unused

    float* out = (float*)d_out;

    const int nrows = in_sizes[0] / DM;                       // 16384
    const unsigned total_slots = (unsigned)nrows * NPTS / 4u; // 5419008
    const unsigned blocks = total_slots / (2u * NTHR);        // 10584, exact
    mvn_fused_kernel<<<blocks, NTHR>>>(rep, dxyz, Wm, bm, Ws, bs, out);
}

// round 8
// speedup vs baseline: 1.0314x; 1.0314x over previous
#include <cuda_runtime.h>
#include <cstdint>

#define DM         64
#define NPTS       1323
#define MAXROWS    16384
#define NTHR       256
#define TILE_SLOTS 256                        // slots per tile; 1 slot = 4 pts = 48B
#define TILE_BYTES (TILE_SLOTS * 48)          // 12288

// param records: 12 floats per row (3 float4): m0,m1,m2,iL00 | L10,iL11,L20,L21 | iL22,C,pad,pad
__device__ float g_params[MAXROWS * 12];

__device__ __forceinline__ uint32_t smem_u32(const void* p) {
    uint32_t a;
    asm("{ .reg .u64 t; cvta.to.shared.u64 t, %1; cvt.u32.u64 %0, t; }" : "=r"(a) : "l"(p));
    return a;
}

__device__ __forceinline__ void mbar_init(uint32_t mbar, uint32_t count) {
    asm volatile("mbarrier.init.shared.b64 [%0], %1;" :: "r"(mbar), "r"(count) : "memory");
}
__device__ __forceinline__ void mbar_expect_tx(uint32_t mbar, uint32_t bytes) {
    asm volatile("mbarrier.arrive.expect_tx.shared.b64 _, [%0], %1;" :: "r"(mbar), "r"(bytes) : "memory");
}
__device__ __forceinline__ void bulk_g2s(uint32_t dst, const void* src, uint32_t bytes, uint32_t mbar) {
    asm volatile("cp.async.bulk.shared::cta.global.mbarrier::complete_tx::bytes [%0], [%1], %2, [%3];"
                 :: "r"(dst), "l"(src), "r"(bytes), "r"(mbar) : "memory");
}
__device__ __forceinline__ void mbar_wait(uint32_t mbar, uint32_t parity) {
    uint32_t done;
    asm volatile("{ .reg .pred p; mbarrier.try_wait.parity.acquire.cta.shared::cta.b64 p, [%1], %2; selp.b32 %0,1,0,p; }"
                 : "=r"(done) : "r"(mbar), "r"(parity) : "memory");
    if (!done) {
        asm volatile("{ .reg .pred P1; WL%=: mbarrier.try_wait.parity.acquire.cta.shared::cta.b64 P1, [%0], %1, 0x989680; @P1 bra.uni WD%=; bra.uni WL%=; WD%=: }"
                     :: "r"(mbar), "r"(parity) : "memory");
    }
}

// ---------------- Kernel A: per-row parameters (one warp per row) ----------------
__global__ __launch_bounds__(NTHR) void mvn_params_kernel(
    const float* __restrict__ rep,
    const float* __restrict__ Wm,
    const float* __restrict__ bm,
    const float* __restrict__ Ws,
    const float* __restrict__ bs,
    int nrows)
{
    cudaTriggerProgrammaticLaunchCompletion();

    const int warp = (blockIdx.x * NTHR + threadIdx.x) >> 5;
    const int lane = threadIdx.x & 31;
    if (warp >= nrows) return;

    const float2 v = ((const float2*)(rep + (size_t)warp * DM))[lane];

    float dots[9];
    #pragma unroll
    for (int c = 0; c < 9; c++) {
        const float* w = (c < 3) ? (Wm + c * DM) : (Ws + (c - 3) * DM);
        const float2 wv = ((const float2*)w)[lane];
        float partial = fmaf(v.x, wv.x, v.y * wv.y);
        #pragma unroll
        for (int off = 16; off > 0; off >>= 1)
            partial += __shfl_xor_sync(0xFFFFFFFFu, partial, off);
        dots[c] = partial;      // full sum on every lane
    }

    float sig = 0.0f, splus = 0.0f;
    if (lane < 6) {
        sig = 1.0f / (1.0f + __expf(-(dots[3 + lane] + bs[lane])));
        splus = __logf(1.0f + __expf(sig));     // sig in (0,1): always safe
    }
    const float L00 = __shfl_sync(0xFFFFFFFFu, splus, 0);
    const float L10 = __shfl_sync(0xFFFFFFFFu, sig,   1);
    const float L11 = __shfl_sync(0xFFFFFFFFu, splus, 2);
    const float L20 = __shfl_sync(0xFFFFFFFFu, sig,   3);
    const float L21 = __shfl_sync(0xFFFFFFFFu, sig,   4);
    const float L22 = __shfl_sync(0xFFFFFFFFu, splus, 5);

    if (lane == 0) {
        const float TWO_PI_1P5 = 15.749609945722419f;   // (2*pi)^1.5
        float C = 1.0f / (L00 * L11 * L22 * TWO_PI_1P5);
        float4* q = (float4*)(g_params + warp * 12);
        q[0] = make_float4(dots[0] + bm[0], dots[1] + bm[1], dots[2] + bm[2], 1.0f / L00);
        q[1] = make_float4(L10, 1.0f / L11, L20, L21);
        q[2] = make_float4(1.0f / L22, C, 0.0f, 0.0f);
    }
}

// one point through the inverse-Cholesky transform + gaussian
__device__ __forceinline__ float mvn_pt(float d0, float d1, float d2,
                                        float4 qa, float4 qb, float4 qc)
{
    d0 -= qa.x;
    d1 -= qa.y;
    d2 -= qa.z;
    float z0 = d0 * qa.w;
    float z1 = (d1 - qb.x * z0) * qb.y;
    float z2 = fmaf(-qb.w, z1, fmaf(-qb.z, z0, d2)) * qc.x;
    float maha = fmaf(z0, z0, fmaf(z1, z1, z2 * z2));
    return qc.y * __expf(-0.5f * maha);
}

// process one slot (4 points packed in 3 float4) given its global slot index
__device__ __forceinline__ float4 mvn_slot(unsigned s, float4 a, float4 b, float4 c)
{
    const unsigned p0 = 4u * s;
    // exact p/1323 for p < ~2e9 (magic: ceil(2^40/1323) = 831074549)
    const unsigned r0 = (unsigned)(((unsigned long long)p0 * 831074549ull) >> 40);
    const unsigned r3 = (unsigned)(((unsigned long long)(p0 + 3u) * 831074549ull) >> 40);

    const float4* __restrict__ P = (const float4*)g_params;
    const float4 qa = __ldg(P + 3u * r0 + 0);
    const float4 qb = __ldg(P + 3u * r0 + 1);
    const float4 qc = __ldg(P + 3u * r0 + 2);

    float4 res;
    if (r0 == r3) {
        // fast path (99.7%)
        res.x = mvn_pt(a.x, a.y, a.z, qa, qb, qc);
        res.y = mvn_pt(a.w, b.x, b.y, qa, qb, qc);
        res.z = mvn_pt(b.z, b.w, c.x, qa, qb, qc);
        res.w = mvn_pt(c.y, c.z, c.w, qa, qb, qc);
    } else {
        // slot crosses a row boundary: points >= E use row r3's params
        const unsigned E = (r0 + 1u) * (unsigned)NPTS;
        const float4 qa2 = __ldg(P + 3u * r3 + 0);
        const float4 qb2 = __ldg(P + 3u * r3 + 1);
        const float4 qc2 = __ldg(P + 3u * r3 + 2);
        res.x = (p0 + 0 < E) ? mvn_pt(a.x, a.y, a.z, qa, qb, qc)
                             : mvn_pt(a.x, a.y, a.z, qa2, qb2, qc2);
        res.y = (p0 + 1 < E) ? mvn_pt(a.w, b.x, b.y, qa, qb, qc)
                             : mvn_pt(a.w, b.x, b.y, qa2, qb2, qc2);
        res.z = (p0 + 2 < E) ? mvn_pt(b.z, b.w, c.x, qa, qb, qc)
                             : mvn_pt(b.z, b.w, c.x, qa2, qb2, qc2);
        res.w = (p0 + 3 < E) ? mvn_pt(c.y, c.z, c.w, qa, qb, qc)
                             : mvn_pt(c.y, c.z, c.w, qa2, qb2, qc2);
    }
    return res;
}

// ---------------- Kernel B: bulk-async staged streaming (2 tiles per block) ----------------
__global__ __launch_bounds__(NTHR) void mvn_stream_kernel(
    const float* __restrict__ dxyz,
    float* __restrict__ out)
{
    __shared__ __align__(1024) float4 sd[2][TILE_SLOTS * 3];   // 2 x 12KB
    __shared__ __align__(8) uint64_t mbar[2];

    const int t = threadIdx.x;
    const unsigned sB = blockIdx.x * (2u * TILE_SLOTS);        // first slot of tile 0

    const uint32_t mb0 = smem_u32(&mbar[0]);
    const uint32_t mb1 = smem_u32(&mbar[1]);

    if (t == 0) {
        mbar_init(mb0, 1);
        mbar_init(mb1, 1);
    }
    __syncthreads();

    // issue both A-independent bulk loads (GMEM -> SMEM, bypasses L1/registers)
    if (t == 0) {
        const char* src = (const char*)(dxyz + (size_t)sB * 12u);
        mbar_expect_tx(mb0, TILE_BYTES);
        bulk_g2s(smem_u32(&sd[0][0]), src, TILE_BYTES, mb0);
        mbar_expect_tx(mb1, TILE_BYTES);
        bulk_g2s(smem_u32(&sd[1][0]), src + TILE_BYTES, TILE_BYTES, mb1);
    }

    // PDL: wait for kernel A's params (overlaps the in-flight bulk copies)
    cudaGridDependencySynchronize();

    // tile 0
    mbar_wait(mb0, 0);
    {
        const float4 a = sd[0][3 * t + 0];
        const float4 b = sd[0][3 * t + 1];
        const float4 c = sd[0][3 * t + 2];
        __stcs((float4*)out + sB + t, mvn_slot(sB + t, a, b, c));
    }

    // tile 1
    mbar_wait(mb1, 0);
    {
        const float4 a = sd[1][3 * t + 0];
        const float4 b = sd[1][3 * t + 1];
        const float4 c = sd[1][3 * t + 2];
        const unsigned s1 = sB + TILE_SLOTS + t;
        __stcs((float4*)out + s1, mvn_slot(s1, a, b, c));
    }
}

extern "C" void kernel_launch(void* const* d_in, const int* in_sizes, int n_in,
                              void* d_out, int out_size)
{
    const float* rep  = (const float*)d_in[0];
    const float* dxyz = (const float*)d_in[1];
    const float* Wm   = (const float*)d_in[2];
    const float* bm   = (const float*)d_in[3];
    const float* Ws   = (const float*)d_in[4];
    const float* bs   = (const float*)d_in[5];
    // d_in[6] = num_planes (fixed 3) — unused

    float* out = (float*)d_out;

    int nrows = in_sizes[0] / DM;          // 16384
    if (nrows > MAXROWS) nrows = MAXROWS;

    // Kernel A: 8 rows per 256-thread block; triggers PDL completion at entry
    const int blkA = (nrows * 32 + NTHR - 1) / NTHR;
    mvn_params_kernel<<<blkA, NTHR>>>(rep, Wm, bm, Ws, bs, nrows);

    // Kernel B: PDL launch; 512 slots per block; 5419008/512 = 10584 exact
    const unsigned total_slots = (unsigned)nrows * NPTS / 4u;
    const unsigned blkB = total_slots / (2u * TILE_SLOTS);

    cudaLaunchConfig_t cfg = {};
    cfg.gridDim  = dim3(blkB, 1, 1);
    cfg.blockDim = dim3(NTHR, 1, 1);
    cfg.dynamicSmemBytes = 0;
    cudaLaunchAttribute attrs[1];
    attrs[0].id = cudaLaunchAttributeProgrammaticStreamSerialization;
    attrs[0].val.programmaticStreamSerializationAllowed = 1;
    cfg.attrs = attrs;
    cfg.numAttrs = 1;
    cudaLaunchKernelEx(&cfg, mvn_stream_kernel, dxyz, out);
}

// round 9
// speedup vs baseline: 1.1544x; 1.1193x over previous
#include <cuda_runtime.h>

#define DM     64
#define NPTS   1323
#define NTHR   256
#define SPT    8                         // slots per thread
#define SPB    (NTHR * SPT)              // 2048 slots per block = 8192 points
#define MAXR   8                         // rows a block can span (ceil(8192/1323)+1 = 8)

// exact p/1323 for p < ~2^31 (magic: ceil(2^40/1323) = 831074549)
__device__ __forceinline__ unsigned rowof(unsigned p) {
    return (unsigned)(((unsigned long long)p * 831074549ull) >> 40);
}

// one point through the inverse-Cholesky transform + gaussian
__device__ __forceinline__ float mvn_pt(float d0, float d1, float d2,
                                        float4 qa, float4 qb, float4 qc)
{
    d0 -= qa.x;
    d1 -= qa.y;
    d2 -= qa.z;
    float z0 = d0 * qa.w;
    float z1 = (d1 - qb.x * z0) * qb.y;
    float z2 = fmaf(-qb.w, z1, fmaf(-qb.z, z0, d2)) * qc.x;
    float maha = fmaf(z0, z0, fmaf(z1, z1, z2 * z2));
    return qc.y * __expf(-0.5f * maha);
}

__global__ __launch_bounds__(NTHR) void mvn_fused_kernel(
    const float* __restrict__ rep,
    const float* __restrict__ dxyz,
    const float* __restrict__ Wm,
    const float* __restrict__ bm,
    const float* __restrict__ bs_,   // note: W_scale/b_scale order per metadata
    const float* __restrict__ Ws,
    float* __restrict__ out,
    int nrows)
{
    __shared__ float4 sqa[MAXR], sqb[MAXR], sqc[MAXR];   // per-row params

    const int t = threadIdx.x;
    const int wid = t >> 5, lane = t & 31;

    const unsigned sBase = blockIdx.x * (unsigned)SPB;
    const unsigned r_first = rowof(4u * sBase);

    // ---- issue first pipeline-stage loads BEFORE the prologue (A-independent) ----
    const float4* __restrict__ dp4 = (const float4*)dxyz;
    unsigned sCur = sBase + (unsigned)t;
    float4 a = __ldcs(dp4 + 3u * (size_t)sCur + 0);
    float4 b = __ldcs(dp4 + 3u * (size_t)sCur + 1);
    float4 c = __ldcs(dp4 + 3u * (size_t)sCur + 2);

    // ---- prologue: warp w computes params for row r_first + w (all warps parallel) ----
    {
        int r = (int)r_first + wid;
        if (r > nrows - 1) r = nrows - 1;
        const float2 v = ((const float2*)(rep + (size_t)r * DM))[lane];

        float dots[9];
        #pragma unroll
        for (int cc = 0; cc < 9; cc++) {
            const float* w = (cc < 3) ? (Wm + cc * DM) : (Ws + (cc - 3) * DM);
            const float2 wv = ((const float2*)w)[lane];
            float partial = fmaf(v.x, wv.x, v.y * wv.y);
            #pragma unroll
            for (int off = 16; off > 0; off >>= 1)
                partial += __shfl_xor_sync(0xFFFFFFFFu, partial, off);
            dots[cc] = partial;   // full sum on every lane
        }

        // lanes 0..5: sigmoid + softplus in parallel
        float sig = 0.0f, splus = 0.0f;
        if (lane < 6) {
            sig = 1.0f / (1.0f + __expf(-(dots[3 + lane] + bs_[lane])));
            splus = __logf(1.0f + __expf(sig));   // sig in (0,1): always safe
        }
        const float L00 = __shfl_sync(0xFFFFFFFFu, splus, 0);
        const float L10 = __shfl_sync(0xFFFFFFFFu, sig,   1);
        const float L11 = __shfl_sync(0xFFFFFFFFu, splus, 2);
        const float L20 = __shfl_sync(0xFFFFFFFFu, sig,   3);
        const float L21 = __shfl_sync(0xFFFFFFFFu, sig,   4);
        const float L22 = __shfl_sync(0xFFFFFFFFu, splus, 5);

        if (lane == 0) {
            const float TWO_PI_1P5 = 15.749609945722419f;   // (2*pi)^1.5
            const float C = 1.0f / (L00 * L11 * L22 * TWO_PI_1P5);
            sqa[wid] = make_float4(dots[0] + bm[0], dots[1] + bm[1], dots[2] + bm[2],
                                   1.0f / L00);
            sqb[wid] = make_float4(L10, 1.0f / L11, L20, L21);
            sqc[wid] = make_float4(1.0f / L22, C, 0.0f, 0.0f);
        }
    }
    __syncthreads();

    // ---- streaming: 8 slots per thread, 2-deep software pipeline ----
    #pragma unroll
    for (int i = 0; i < SPT; i++) {
        // prefetch next slot while computing this one
        float4 an, bn, cn;
        const unsigned sNext = sCur + NTHR;
        if (i + 1 < SPT) {
            an = __ldcs(dp4 + 3u * (size_t)sNext + 0);
            bn = __ldcs(dp4 + 3u * (size_t)sNext + 1);
            cn = __ldcs(dp4 + 3u * (size_t)sNext + 2);
        }

        const unsigned p0 = 4u * sCur;
        const unsigned r0 = rowof(p0);
        const unsigned r3 = rowof(p0 + 3u);
        const int i0 = (int)(r0 - r_first);

        const float4 qa = sqa[i0], qb = sqb[i0], qc = sqc[i0];

        float4 res;
        if (r0 == r3) {
            // fast path (99.7%)
            res.x = mvn_pt(a.x, a.y, a.z, qa, qb, qc);
            res.y = mvn_pt(a.w, b.x, b.y, qa, qb, qc);
            res.z = mvn_pt(b.z, b.w, c.x, qa, qb, qc);
            res.w = mvn_pt(c.y, c.z, c.w, qa, qb, qc);
        } else {
            // slot crosses a row boundary: points >= E use row r3's params
            const unsigned E = (r0 + 1u) * (unsigned)NPTS;
            const int i3 = (int)(r3 - r_first);
            const float4 qa2 = sqa[i3], qb2 = sqb[i3], qc2 = sqc[i3];
            res.x = (p0 + 0 < E) ? mvn_pt(a.x, a.y, a.z, qa, qb, qc)
                                 : mvn_pt(a.x, a.y, a.z, qa2, qb2, qc2);
            res.y = (p0 + 1 < E) ? mvn_pt(a.w, b.x, b.y, qa, qb, qc)
                                 : mvn_pt(a.w, b.x, b.y, qa2, qb2, qc2);
            res.z = (p0 + 2 < E) ? mvn_pt(b.z, b.w, c.x, qa, qb, qc)
                                 : mvn_pt(b.z, b.w, c.x, qa2, qb2, qc2);
            res.w = (p0 + 3 < E) ? mvn_pt(c.y, c.z, c.w, qa, qb, qc)
                                 : mvn_pt(c.y, c.z, c.w, qa2, qb2, qc2);
        }

        __stcs((float4*)out + sCur, res);

        a = an; b = bn; c = cn;
        sCur = sNext;
    }
}

extern "C" void kernel_launch(void* const* d_in, const int* in_sizes, int n_in,
                              void* d_out, int out_size)
{
    const float* rep  = (const float*)d_in[0];
    const float* dxyz = (const float*)d_in[1];
    const float* Wm   = (const float*)d_in[2];
    const float* bm   = (const float*)d_in[3];
    const float* Ws   = (const float*)d_in[4];
    const float* bs   = (const float*)d_in[5];
    // d_in[6] = num_planes (fixed 3) — unused

    float* out = (float*)d_out;

    const int nrows = in_sizes[0] / DM;                       // 16384
    const unsigned total_slots = (unsigned)nrows * NPTS / 4u; // 5419008
    const unsigned blocks = total_slots / SPB;                // 2646, exact
    mvn_fused_kernel<<<blocks, NTHR>>>(rep, dxyz, Wm, bm, bs, Ws, out, nrows);
}

// round 10
// speedup vs baseline: 1.1821x; 1.0240x over previous
#include <cuda_runtime.h>

#define DM     64
#define NPTS   1323
#define NTHR   256
#define SPT    8                         // slots per thread
#define SPB    (NTHR * SPT)              // 2048 slots per block = 8192 points
#define MAXR   8                         // rows a block can span

// exact p/1323 for p < ~2^31 (magic: ceil(2^40/1323) = 831074549)
__device__ __forceinline__ unsigned rowof(unsigned p) {
    return (unsigned)(((unsigned long long)p * 831074549ull) >> 40);
}

// one point through the inverse-Cholesky transform + gaussian
__device__ __forceinline__ float mvn_pt(float d0, float d1, float d2,
                                        float4 qa, float4 qb, float4 qc)
{
    d0 -= qa.x;
    d1 -= qa.y;
    d2 -= qa.z;
    float z0 = d0 * qa.w;
    float z1 = (d1 - qb.x * z0) * qb.y;
    float z2 = fmaf(-qb.w, z1, fmaf(-qb.z, z0, d2)) * qc.x;
    float maha = fmaf(z0, z0, fmaf(z1, z1, z2 * z2));
    return qc.y * __expf(-0.5f * maha);
}

struct SmemP { float4 qa[MAXR], qb[MAXR], qc[MAXR]; };

// one slot given staged data; params from block-local smem table
__device__ __forceinline__ float4 mvn_slot(unsigned s, unsigned r_first,
                                           float4 a, float4 b, float4 c,
                                           const SmemP* sp)
{
    const unsigned p0 = 4u * s;
    const unsigned r0 = rowof(p0);
    const unsigned r3 = rowof(p0 + 3u);
    const int i0 = (int)(r0 - r_first);

    const float4 qa = sp->qa[i0], qb = sp->qb[i0], qc = sp->qc[i0];

    float4 res;
    if (r0 == r3) {
        // fast path (99.7%)
        res.x = mvn_pt(a.x, a.y, a.z, qa, qb, qc);
        res.y = mvn_pt(a.w, b.x, b.y, qa, qb, qc);
        res.z = mvn_pt(b.z, b.w, c.x, qa, qb, qc);
        res.w = mvn_pt(c.y, c.z, c.w, qa, qb, qc);
    } else {
        // slot crosses a row boundary: points >= E use row r3's params
        const unsigned E = (r0 + 1u) * (unsigned)NPTS;
        const int i3 = (int)(r3 - r_first);
        const float4 qa2 = sp->qa[i3], qb2 = sp->qb[i3], qc2 = sp->qc[i3];
        res.x = (p0 + 0 < E) ? mvn_pt(a.x, a.y, a.z, qa, qb, qc)
                             : mvn_pt(a.x, a.y, a.z, qa2, qb2, qc2);
        res.y = (p0 + 1 < E) ? mvn_pt(a.w, b.x, b.y, qa, qb, qc)
                             : mvn_pt(a.w, b.x, b.y, qa2, qb2, qc2);
        res.z = (p0 + 2 < E) ? mvn_pt(b.z, b.w, c.x, qa, qb, qc)
                             : mvn_pt(b.z, b.w, c.x, qa2, qb2, qc2);
        res.w = (p0 + 3 < E) ? mvn_pt(c.y, c.z, c.w, qa, qb, qc)
                             : mvn_pt(c.y, c.z, c.w, qa2, qb2, qc2);
    }
    return res;
}

__global__ __launch_bounds__(NTHR) void mvn_fused_kernel(
    const float* __restrict__ rep,
    const float* __restrict__ dxyz,
    const float* __restrict__ Wm,
    const float* __restrict__ bm,
    const float* __restrict__ bs_,
    const float* __restrict__ Ws,
    float* __restrict__ out,
    int nrows)
{
    __shared__ SmemP sp;

    const int t = threadIdx.x;
    const int wid = t >> 5, lane = t & 31;

    const unsigned sBase = blockIdx.x * (unsigned)SPB;
    const unsigned r_first = rowof(4u * sBase);

    const float4* __restrict__ dp4 = (const float4*)dxyz;

    // ---- issue the first PAIR's 6 loads before the prologue ----
    unsigned s0 = sBase + (unsigned)t;
    unsigned s1 = s0 + NTHR;
    float4 a0 = __ldcs(dp4 + 3u * (size_t)s0 + 0);
    float4 b0 = __ldcs(dp4 + 3u * (size_t)s0 + 1);
    float4 c0 = __ldcs(dp4 + 3u * (size_t)s0 + 2);
    float4 a1 = __ldcs(dp4 + 3u * (size_t)s1 + 0);
    float4 b1 = __ldcs(dp4 + 3u * (size_t)s1 + 1);
    float4 c1 = __ldcs(dp4 + 3u * (size_t)s1 + 2);

    // ---- prologue: warp w computes params for row r_first + w (all warps parallel) ----
    {
        int r = (int)r_first + wid;
        if (r > nrows - 1) r = nrows - 1;
        const float2 v = ((const float2*)(rep + (size_t)r * DM))[lane];

        float dots[9];
        #pragma unroll
        for (int cc = 0; cc < 9; cc++) {
            const float* w = (cc < 3) ? (Wm + cc * DM) : (Ws + (cc - 3) * DM);
            const float2 wv = ((const float2*)w)[lane];
            float partial = fmaf(v.x, wv.x, v.y * wv.y);
            #pragma unroll
            for (int off = 16; off > 0; off >>= 1)
                partial += __shfl_xor_sync(0xFFFFFFFFu, partial, off);
            dots[cc] = partial;   // full sum on every lane
        }

        float sig = 0.0f, splus = 0.0f;
        if (lane < 6) {
            sig = 1.0f / (1.0f + __expf(-(dots[3 + lane] + bs_[lane])));
            splus = __logf(1.0f + __expf(sig));   // sig in (0,1): always safe
        }
        const float L00 = __shfl_sync(0xFFFFFFFFu, splus, 0);
        const float L10 = __shfl_sync(0xFFFFFFFFu, sig,   1);
        const float L11 = __shfl_sync(0xFFFFFFFFu, splus, 2);
        const float L20 = __shfl_sync(0xFFFFFFFFu, sig,   3);
        const float L21 = __shfl_sync(0xFFFFFFFFu, sig,   4);
        const float L22 = __shfl_sync(0xFFFFFFFFu, splus, 5);

        if (lane == 0) {
            const float TWO_PI_1P5 = 15.749609945722419f;   // (2*pi)^1.5
            const float C = 1.0f / (L00 * L11 * L22 * TWO_PI_1P5);
            sp.qa[wid] = make_float4(dots[0] + bm[0], dots[1] + bm[1], dots[2] + bm[2],
                                     1.0f / L00);
            sp.qb[wid] = make_float4(L10, 1.0f / L11, L20, L21);
            sp.qc[wid] = make_float4(1.0f / L22, C, 0.0f, 0.0f);
        }
    }
    __syncthreads();

    // ---- streaming: 4 iterations x 2 slots; 6 loads issued back-to-back per pair ----
    #pragma unroll
    for (int i = 0; i < SPT / 2; i++) {
        const float4 r0 = mvn_slot(s0, r_first, a0, b0, c0, &sp);
        const float4 r1 = mvn_slot(s1, r_first, a1, b1, c1, &sp);
        __stcs((float4*)out + s0, r0);
        __stcs((float4*)out + s1, r1);

        if (i + 1 < SPT / 2) {
            s0 += 2u * NTHR;
            s1 += 2u * NTHR;
            a0 = __ldcs(dp4 + 3u * (size_t)s0 + 0);
            b0 = __ldcs(dp4 + 3u * (size_t)s0 + 1);
            c0 = __ldcs(dp4 + 3u * (size_t)s0 + 2);
            a1 = __ldcs(dp4 + 3u * (size_t)s1 + 0);
            b1 = __ldcs(dp4 + 3u * (size_t)s1 + 1);
            c1 = __ldcs(dp4 + 3u * (size_t)s1 + 2);
        }
    }
}

extern "C" void kernel_launch(void* const* d_in, const int* in_sizes, int n_in,
                              void* d_out, int out_size)
{
    const float* rep  = (const float*)d_in[0];
    const float* dxyz = (const float*)d_in[1];
    const float* Wm   = (const float*)d_in[2];
    const float* bm   = (const float*)d_in[3];
    const float* Ws   = (const float*)d_in[4];
    const float* bs   = (const float*)d_in[5];
    // d_in[6] = num_planes (fixed 3) — unused

    float* out = (float*)d_out;

    const int nrows = in_sizes[0] / DM;                       // 16384
    const unsigned total_slots = (unsigned)nrows * NPTS / 4u; // 5419008
    const unsigned blocks = total_slots / SPB;                // 2646, exact
    mvn_fused_kernel<<<blocks, NTHR>>>(rep, dxyz, Wm, bm, bs, Ws, out, nrows);
}